// round 1
// baseline (speedup 1.0000x reference)
#include <cuda_runtime.h>
#include <cstddef>

#define NN 131072
#define KK 27
#define FIN 3
#define FOUT 32
#define EPSV 1e-5f

// scratch (device globals — no allocation allowed)
__device__ float g_h[(size_t)NN * FOUT];
__device__ float g_z[(size_t)NN * FOUT];

// ---------------------------------------------------------------------------
// Stage 1: h = silu(bn1(einsum(x[nbr], w1)));  z = relu(bn2(z_feats@mlp_w+b))
// ---------------------------------------------------------------------------
__global__ __launch_bounds__(256) void stage1_kernel(
    const float* __restrict__ x_feats,
    const float* __restrict__ z_feats,
    const int*   __restrict__ nbr,
    const float* __restrict__ w1,
    const float* __restrict__ bn1_gamma,
    const float* __restrict__ bn1_beta,
    const float* __restrict__ bn1_mean,
    const float* __restrict__ bn1_var,
    const float* __restrict__ mlp_w,
    const float* __restrict__ mlp_b,
    const float* __restrict__ mlp_gamma,
    const float* __restrict__ mlp_beta,
    const float* __restrict__ mlp_mean,
    const float* __restrict__ mlp_var)
{
    __shared__ float w1s[KK * FIN * FOUT];   // 27*3*32 = 2592 floats
    __shared__ float mws[FIN * FOUT];
    __shared__ float s1[FOUT], t1[FOUT], s2[FOUT], t2[FOUT], mbs[FOUT];

    const int tid = threadIdx.x;
    for (int i = tid; i < KK * FIN * FOUT; i += 256) w1s[i] = w1[i];
    for (int i = tid; i < FIN * FOUT; i += 256) mws[i] = mlp_w[i];
    if (tid < FOUT) {
        float s = bn1_gamma[tid] * rsqrtf(bn1_var[tid] + EPSV);
        s1[tid] = s;
        t1[tid] = bn1_beta[tid] - bn1_mean[tid] * s;
        float q = mlp_gamma[tid] * rsqrtf(mlp_var[tid] + EPSV);
        s2[tid] = q;
        t2[tid] = mlp_beta[tid] - mlp_mean[tid] * q;
        mbs[tid] = mlp_b[tid];
    }
    __syncthreads();

    const int n = blockIdx.x * 256 + tid;
    if (n >= NN) return;

    float acc[FOUT];

    // ---- point branch: z = relu(bn(z_feats @ mlp_w + b)) ----
    {
        const float zf0 = z_feats[(size_t)n * 3 + 0];
        const float zf1 = z_feats[(size_t)n * 3 + 1];
        const float zf2 = z_feats[(size_t)n * 3 + 2];
        #pragma unroll
        for (int o = 0; o < FOUT; o++) {
            float v = zf0 * mws[o] + zf1 * mws[FOUT + o] + zf2 * mws[2 * FOUT + o] + mbs[o];
            v = v * s2[o] + t2[o];
            acc[o] = fmaxf(v, 0.0f);
        }
        float4* zp = (float4*)&g_z[(size_t)n * FOUT];
        #pragma unroll
        for (int i = 0; i < 8; i++)
            zp[i] = make_float4(acc[4*i], acc[4*i+1], acc[4*i+2], acc[4*i+3]);
    }

    // ---- voxel branch stage 1 ----
    #pragma unroll
    for (int o = 0; o < FOUT; o++) acc[o] = 0.0f;

    const int* nrow = nbr + (size_t)n * KK;
    #pragma unroll 1
    for (int k = 0; k < KK; k++) {
        const int j = nrow[k];
        const float x0 = __ldg(&x_feats[(size_t)j * 3 + 0]);
        const float x1 = __ldg(&x_feats[(size_t)j * 3 + 1]);
        const float x2 = __ldg(&x_feats[(size_t)j * 3 + 2]);
        const float* w = &w1s[k * FIN * FOUT];
        #pragma unroll
        for (int o = 0; o < FOUT; o++) {
            acc[o] += x0 * w[o] + x1 * w[FOUT + o] + x2 * w[2 * FOUT + o];
        }
    }

    #pragma unroll
    for (int o = 0; o < FOUT; o++) {
        float v = acc[o] * s1[o] + t1[o];
        // SiLU
        v = v / (1.0f + __expf(-v));
        acc[o] = v;
    }
    float4* hp = (float4*)&g_h[(size_t)n * FOUT];
    #pragma unroll
    for (int i = 0; i < 8; i++)
        hp[i] = make_float4(acc[4*i], acc[4*i+1], acc[4*i+2], acc[4*i+3]);
}

// ---------------------------------------------------------------------------
// Stage 2: out = einsum(h[nbr], w2) + z ; written to both output halves
// ---------------------------------------------------------------------------
__global__ __launch_bounds__(256) void stage2_kernel(
    const int*   __restrict__ nbr,
    const float* __restrict__ w2,
    float*       __restrict__ out,
    size_t half)
{
    extern __shared__ float w2s[];   // 27*32*32 = 27648 floats = 110592 B
    for (int i = threadIdx.x; i < KK * FOUT * FOUT; i += 256) w2s[i] = w2[i];
    __syncthreads();

    const int n = blockIdx.x * 256 + threadIdx.x;
    if (n >= NN) return;

    float acc[FOUT];
    // init accumulator with point-branch z
    {
        const float4* zp = (const float4*)&g_z[(size_t)n * FOUT];
        #pragma unroll
        for (int i = 0; i < 8; i++) {
            float4 v = zp[i];
            acc[4*i+0] = v.x; acc[4*i+1] = v.y; acc[4*i+2] = v.z; acc[4*i+3] = v.w;
        }
    }

    const int* nrow = nbr + (size_t)n * KK;
    #pragma unroll 1
    for (int k = 0; k < KK; k++) {
        const int j = nrow[k];
        float row[FOUT];
        const float4* hp = (const float4*)&g_h[(size_t)j * FOUT];
        #pragma unroll
        for (int i = 0; i < 8; i++) {
            float4 v = __ldg(&hp[i]);
            row[4*i+0] = v.x; row[4*i+1] = v.y; row[4*i+2] = v.z; row[4*i+3] = v.w;
        }
        const float* w = &w2s[k * FOUT * FOUT];
        #pragma unroll
        for (int f = 0; f < FOUT; f++) {
            const float hv = row[f];
            #pragma unroll
            for (int o = 0; o < FOUT; o++) {
                acc[o] += hv * w[f * FOUT + o];
            }
        }
    }

    float4* o1 = (float4*)(out + (size_t)n * FOUT);
    float4* o2 = (float4*)(out + half + (size_t)n * FOUT);
    #pragma unroll
    for (int i = 0; i < 8; i++) {
        float4 v = make_float4(acc[4*i], acc[4*i+1], acc[4*i+2], acc[4*i+3]);
        o1[i] = v;
        o2[i] = v;
    }
}

// ---------------------------------------------------------------------------
extern "C" void kernel_launch(void* const* d_in, const int* in_sizes, int n_in,
                              void* d_out, int out_size)
{
    const float* x_feats   = (const float*)d_in[0];
    const float* z_feats   = (const float*)d_in[1];
    const int*   nbr_idx   = (const int*)  d_in[2];
    const float* w1        = (const float*)d_in[3];
    const float* bn1_gamma = (const float*)d_in[4];
    const float* bn1_beta  = (const float*)d_in[5];
    const float* bn1_mean  = (const float*)d_in[6];
    const float* bn1_var   = (const float*)d_in[7];
    const float* w2        = (const float*)d_in[8];
    const float* mlp_w     = (const float*)d_in[9];
    const float* mlp_b     = (const float*)d_in[10];
    const float* mlp_gamma = (const float*)d_in[11];
    const float* mlp_beta  = (const float*)d_in[12];
    const float* mlp_mean  = (const float*)d_in[13];
    const float* mlp_var   = (const float*)d_in[14];

    float* out = (float*)d_out;
    const size_t half = (size_t)out_size / 2;

    const int threads = 256;
    const int blocks = (NN + threads - 1) / threads;

    static bool attr_done = false;
    const int smem2 = KK * FOUT * FOUT * (int)sizeof(float);  // 110592 B
    if (!attr_done) {
        cudaFuncSetAttribute(stage2_kernel,
                             cudaFuncAttributeMaxDynamicSharedMemorySize, smem2);
        attr_done = true;
    }

    stage1_kernel<<<blocks, threads>>>(x_feats, z_feats, nbr_idx, w1,
                                       bn1_gamma, bn1_beta, bn1_mean, bn1_var,
                                       mlp_w, mlp_b, mlp_gamma, mlp_beta,
                                       mlp_mean, mlp_var);
    stage2_kernel<<<blocks, threads, smem2>>>(nbr_idx, w2, out, half);
}

// round 2
// speedup vs baseline: 1.0206x; 1.0206x over previous
#include <cuda_runtime.h>
#include <cstddef>

#define NN 131072
#define KK 27
#define FIN 3
#define FOUT 32
#define EPSV 1e-5f

// scratch (device globals — no allocation allowed)
__device__ float g_h[(size_t)NN * FOUT];
__device__ float g_z[(size_t)NN * FOUT];

// ---------------------------------------------------------------------------
// Stage 1: h = silu(bn1(einsum(x[nbr], w1)));  z = relu(bn2(z_feats@mlp_w+b))
// ---------------------------------------------------------------------------
__global__ __launch_bounds__(256) void stage1_kernel(
    const float* __restrict__ x_feats,
    const float* __restrict__ z_feats,
    const int*   __restrict__ nbr,
    const float* __restrict__ w1,
    const float* __restrict__ bn1_gamma,
    const float* __restrict__ bn1_beta,
    const float* __restrict__ bn1_mean,
    const float* __restrict__ bn1_var,
    const float* __restrict__ mlp_w,
    const float* __restrict__ mlp_b,
    const float* __restrict__ mlp_gamma,
    const float* __restrict__ mlp_beta,
    const float* __restrict__ mlp_mean,
    const float* __restrict__ mlp_var)
{
    __shared__ float w1s[KK * FIN * FOUT];   // 27*3*32 = 2592 floats
    __shared__ float mws[FIN * FOUT];
    __shared__ float s1[FOUT], t1[FOUT], s2[FOUT], t2[FOUT], mbs[FOUT];

    const int tid = threadIdx.x;
    for (int i = tid; i < KK * FIN * FOUT; i += 256) w1s[i] = w1[i];
    for (int i = tid; i < FIN * FOUT; i += 256) mws[i] = mlp_w[i];
    if (tid < FOUT) {
        float s = bn1_gamma[tid] * rsqrtf(bn1_var[tid] + EPSV);
        s1[tid] = s;
        t1[tid] = bn1_beta[tid] - bn1_mean[tid] * s;
        float q = mlp_gamma[tid] * rsqrtf(mlp_var[tid] + EPSV);
        s2[tid] = q;
        t2[tid] = mlp_beta[tid] - mlp_mean[tid] * q;
        mbs[tid] = mlp_b[tid];
    }
    __syncthreads();

    const int n = blockIdx.x * 256 + tid;
    if (n >= NN) return;

    float acc[FOUT];

    // ---- point branch: z = relu(bn(z_feats @ mlp_w + b)) ----
    {
        const float zf0 = z_feats[(size_t)n * 3 + 0];
        const float zf1 = z_feats[(size_t)n * 3 + 1];
        const float zf2 = z_feats[(size_t)n * 3 + 2];
        #pragma unroll
        for (int o = 0; o < FOUT; o++) {
            float v = zf0 * mws[o] + zf1 * mws[FOUT + o] + zf2 * mws[2 * FOUT + o] + mbs[o];
            v = v * s2[o] + t2[o];
            acc[o] = fmaxf(v, 0.0f);
        }
        float4* zp = (float4*)&g_z[(size_t)n * FOUT];
        #pragma unroll
        for (int i = 0; i < 8; i++)
            zp[i] = make_float4(acc[4*i], acc[4*i+1], acc[4*i+2], acc[4*i+3]);
    }

    // ---- voxel branch stage 1 ----
    #pragma unroll
    for (int o = 0; o < FOUT; o++) acc[o] = 0.0f;

    const int* nrow = nbr + (size_t)n * KK;
    #pragma unroll 1
    for (int k = 0; k < KK; k++) {
        const int j = nrow[k];
        const float x0 = __ldg(&x_feats[(size_t)j * 3 + 0]);
        const float x1 = __ldg(&x_feats[(size_t)j * 3 + 1]);
        const float x2 = __ldg(&x_feats[(size_t)j * 3 + 2]);
        const float* w = &w1s[k * FIN * FOUT];
        #pragma unroll
        for (int o = 0; o < FOUT; o++) {
            acc[o] += x0 * w[o] + x1 * w[FOUT + o] + x2 * w[2 * FOUT + o];
        }
    }

    #pragma unroll
    for (int o = 0; o < FOUT; o++) {
        float v = acc[o] * s1[o] + t1[o];
        // SiLU
        v = v / (1.0f + __expf(-v));
        acc[o] = v;
    }
    float4* hp = (float4*)&g_h[(size_t)n * FOUT];
    #pragma unroll
    for (int i = 0; i < 8; i++)
        hp[i] = make_float4(acc[4*i], acc[4*i+1], acc[4*i+2], acc[4*i+3]);
}

// ---------------------------------------------------------------------------
// Stage 2: out = einsum(h[nbr], w2) + z ; packed f32x2 FFMA + row prefetch
// ---------------------------------------------------------------------------

// One k-slice of the accumulation: acc(pairs) += h_row[f] * w2[k][f][pair]
__device__ __forceinline__ void compute_k(
    const float (&row)[FOUT],
    const float* __restrict__ wk,          // &w2s[k*1024], 16B aligned
    unsigned long long (&acc)[16])
{
    const double2* w = (const double2*)wk;
    #pragma unroll
    for (int f = 0; f < FOUT; f++) {
        unsigned int hu = __float_as_uint(row[f]);
        unsigned long long hp;
        asm("mov.b64 %0, {%1, %1};" : "=l"(hp) : "r"(hu));
        #pragma unroll
        for (int p = 0; p < 8; p++) {
            double2 wv = w[f * 8 + p];                    // LDS.128 (broadcast)
            unsigned long long w0 = __double_as_longlong(wv.x);
            unsigned long long w1 = __double_as_longlong(wv.y);
            asm("fma.rn.f32x2 %0, %1, %2, %0;" : "+l"(acc[2*p])   : "l"(hp), "l"(w0));
            asm("fma.rn.f32x2 %0, %1, %2, %0;" : "+l"(acc[2*p+1]) : "l"(hp), "l"(w1));
        }
    }
}

__device__ __forceinline__ void load_row(float (&buf)[FOUT], int j)
{
    const float4* hp = (const float4*)&g_h[(size_t)j * FOUT];
    #pragma unroll
    for (int i = 0; i < 8; i++) {
        float4 v = __ldg(&hp[i]);
        buf[4*i+0] = v.x; buf[4*i+1] = v.y; buf[4*i+2] = v.z; buf[4*i+3] = v.w;
    }
}

__global__ __launch_bounds__(256, 2) void stage2_kernel(
    const int*   __restrict__ nbr,
    const float* __restrict__ w2,
    float*       __restrict__ out,
    size_t half)
{
    extern __shared__ float w2s[];   // 27*32*32 floats = 110592 B
    {
        const float4* src = (const float4*)w2;
        float4* dst = (float4*)w2s;
        for (int i = threadIdx.x; i < KK * FOUT * FOUT / 4; i += 256)
            dst[i] = src[i];
    }
    __syncthreads();

    const int n = blockIdx.x * 256 + threadIdx.x;
    if (n >= NN) return;

    // accumulator initialized from point-branch z (packed pairs)
    unsigned long long acc[16];
    {
        const ulonglong2* zp = (const ulonglong2*)&g_z[(size_t)n * FOUT];
        #pragma unroll
        for (int i = 0; i < 8; i++) {
            ulonglong2 v = zp[i];
            acc[2*i] = v.x; acc[2*i+1] = v.y;
        }
    }

    const int* nrow = nbr + (size_t)n * KK;

    float bufA[FOUT], bufB[FOUT];
    load_row(bufA, nrow[0]);

    #pragma unroll 1
    for (int k = 0; k < KK - 1; k += 2) {
        const int j1 = nrow[k + 1];
        load_row(bufB, j1);                      // prefetch k+1 while computing k
        compute_k(bufA, w2s + k * (FOUT * FOUT), acc);
        const int j2 = nrow[k + 2];              // k+2 <= 26 always in-range
        load_row(bufA, j2);                      // prefetch k+2 while computing k+1
        compute_k(bufB, w2s + (k + 1) * (FOUT * FOUT), acc);
    }
    compute_k(bufA, w2s + (KK - 1) * (FOUT * FOUT), acc);

    ulonglong2* o1 = (ulonglong2*)(out + (size_t)n * FOUT);
    ulonglong2* o2 = (ulonglong2*)(out + half + (size_t)n * FOUT);
    #pragma unroll
    for (int i = 0; i < 8; i++) {
        ulonglong2 v;
        v.x = acc[2*i]; v.y = acc[2*i+1];
        o1[i] = v;
        o2[i] = v;
    }
}

// ---------------------------------------------------------------------------
extern "C" void kernel_launch(void* const* d_in, const int* in_sizes, int n_in,
                              void* d_out, int out_size)
{
    const float* x_feats   = (const float*)d_in[0];
    const float* z_feats   = (const float*)d_in[1];
    const int*   nbr_idx   = (const int*)  d_in[2];
    const float* w1        = (const float*)d_in[3];
    const float* bn1_gamma = (const float*)d_in[4];
    const float* bn1_beta  = (const float*)d_in[5];
    const float* bn1_mean  = (const float*)d_in[6];
    const float* bn1_var   = (const float*)d_in[7];
    const float* w2        = (const float*)d_in[8];
    const float* mlp_w     = (const float*)d_in[9];
    const float* mlp_b     = (const float*)d_in[10];
    const float* mlp_gamma = (const float*)d_in[11];
    const float* mlp_beta  = (const float*)d_in[12];
    const float* mlp_mean  = (const float*)d_in[13];
    const float* mlp_var   = (const float*)d_in[14];

    float* out = (float*)d_out;
    const size_t half = (size_t)out_size / 2;

    const int threads = 256;
    const int blocks = (NN + threads - 1) / threads;

    static bool attr_done = false;
    const int smem2 = KK * FOUT * FOUT * (int)sizeof(float);  // 110592 B
    if (!attr_done) {
        cudaFuncSetAttribute(stage2_kernel,
                             cudaFuncAttributeMaxDynamicSharedMemorySize, smem2);
        attr_done = true;
    }

    stage1_kernel<<<blocks, threads>>>(x_feats, z_feats, nbr_idx, w1,
                                       bn1_gamma, bn1_beta, bn1_mean, bn1_var,
                                       mlp_w, mlp_b, mlp_gamma, mlp_beta,
                                       mlp_mean, mlp_var);
    stage2_kernel<<<blocks, threads, smem2>>>(nbr_idx, w2, out, half);
}

// round 3
// speedup vs baseline: 1.5239x; 1.4932x over previous
#include <cuda_runtime.h>
#include <cstddef>

#define NN 131072
#define KK 27
#define FIN 3
#define FOUT 32
#define EPSV 1e-5f

// scratch (device globals — no allocation allowed)
__device__ float g_h[(size_t)NN * FOUT];
__device__ float g_z[(size_t)NN * FOUT];
__device__ float4 g_x4[(size_t)NN];           // padded x_feats
__device__ int   g_nbrT[(size_t)KK * NN];     // transposed neighbor indices

// ---------------------------------------------------------------------------
// Prep: pad x_feats to float4, transpose nbr_idx -> [k][n]
// ---------------------------------------------------------------------------
__global__ __launch_bounds__(256) void prep_kernel(
    const float* __restrict__ x_feats,
    const int*   __restrict__ nbr)
{
    const size_t i = (size_t)blockIdx.x * 256 + threadIdx.x;
    if (i < (size_t)NN * KK) {
        const int v = nbr[i];
        const int n = (int)(i / KK);
        const int k = (int)(i % KK);
        g_nbrT[(size_t)k * NN + n] = v;
    }
    if (i < NN) {
        g_x4[i] = make_float4(x_feats[3*i], x_feats[3*i+1], x_feats[3*i+2], 0.0f);
    }
}

// ---------------------------------------------------------------------------
// Stage 1: h = silu(bn1(einsum(x[nbr], w1)));  z = relu(bn2(z@mlp_w+b))
// ---------------------------------------------------------------------------
__global__ __launch_bounds__(256) void stage1_kernel(
    const float* __restrict__ z_feats,
    const float* __restrict__ w1,
    const float* __restrict__ bn1_gamma,
    const float* __restrict__ bn1_beta,
    const float* __restrict__ bn1_mean,
    const float* __restrict__ bn1_var,
    const float* __restrict__ mlp_w,
    const float* __restrict__ mlp_b,
    const float* __restrict__ mlp_gamma,
    const float* __restrict__ mlp_beta,
    const float* __restrict__ mlp_mean,
    const float* __restrict__ mlp_var)
{
    __shared__ __align__(16) float w1s[KK * FIN * FOUT];   // 2592 floats
    __shared__ __align__(16) float mws[FIN * FOUT];
    __shared__ float s1[FOUT], t1[FOUT], s2[FOUT], t2[FOUT], mbs[FOUT];

    const int tid = threadIdx.x;
    for (int i = tid; i < KK * FIN * FOUT; i += 256) w1s[i] = w1[i];
    for (int i = tid; i < FIN * FOUT; i += 256) mws[i] = mlp_w[i];
    if (tid < FOUT) {
        float s = bn1_gamma[tid] * rsqrtf(bn1_var[tid] + EPSV);
        s1[tid] = s;
        t1[tid] = bn1_beta[tid] - bn1_mean[tid] * s;
        float q = mlp_gamma[tid] * rsqrtf(mlp_var[tid] + EPSV);
        s2[tid] = q;
        t2[tid] = mlp_beta[tid] - mlp_mean[tid] * q;
        mbs[tid] = mlp_b[tid];
    }
    __syncthreads();

    const int n = blockIdx.x * 256 + tid;
    if (n >= NN) return;

    // ---- point branch ----
    {
        float acc[FOUT];
        const float zf0 = z_feats[(size_t)n * 3 + 0];
        const float zf1 = z_feats[(size_t)n * 3 + 1];
        const float zf2 = z_feats[(size_t)n * 3 + 2];
        #pragma unroll
        for (int o = 0; o < FOUT; o++) {
            float v = zf0 * mws[o] + zf1 * mws[FOUT + o] + zf2 * mws[2 * FOUT + o] + mbs[o];
            v = v * s2[o] + t2[o];
            acc[o] = fmaxf(v, 0.0f);
        }
        float4* zp = (float4*)&g_z[(size_t)n * FOUT];
        #pragma unroll
        for (int i = 0; i < 8; i++)
            zp[i] = make_float4(acc[4*i], acc[4*i+1], acc[4*i+2], acc[4*i+3]);
    }

    // ---- voxel branch stage 1, packed f32x2 ----
    unsigned long long acc[16];
    #pragma unroll
    for (int i = 0; i < 16; i++) acc[i] = 0ull;

    #pragma unroll 1
    for (int k = 0; k < KK; k++) {
        const int j = g_nbrT[(size_t)k * NN + n];       // coalesced
        const float4 xv = __ldg(&g_x4[j]);              // one LDG.128 per row
        const float xs[3] = {xv.x, xv.y, xv.z};
        const double2* w = (const double2*)&w1s[k * FIN * FOUT];
        #pragma unroll
        for (int f = 0; f < FIN; f++) {
            unsigned int hu = __float_as_uint(xs[f]);
            unsigned long long hp;
            asm("mov.b64 %0, {%1, %1};" : "=l"(hp) : "r"(hu));
            #pragma unroll
            for (int p = 0; p < 8; p++) {
                double2 wv = w[f * 8 + p];
                unsigned long long w0 = __double_as_longlong(wv.x);
                unsigned long long w1v = __double_as_longlong(wv.y);
                asm("fma.rn.f32x2 %0, %1, %2, %0;" : "+l"(acc[2*p])   : "l"(hp), "l"(w0));
                asm("fma.rn.f32x2 %0, %1, %2, %0;" : "+l"(acc[2*p+1]) : "l"(hp), "l"(w1v));
            }
        }
    }

    // BN + SiLU epilogue (scalar)
    float4* hp4 = (float4*)&g_h[(size_t)n * FOUT];
    #pragma unroll
    for (int i = 0; i < 8; i++) {
        float v[4];
        #pragma unroll
        for (int e = 0; e < 2; e++) {
            unsigned long long a = acc[2*i + e];
            unsigned int lo = (unsigned int)(a & 0xffffffffull);
            unsigned int hi = (unsigned int)(a >> 32);
            v[2*e]   = __uint_as_float(lo);
            v[2*e+1] = __uint_as_float(hi);
        }
        #pragma unroll
        for (int e = 0; e < 4; e++) {
            const int o = 4*i + e;
            float t = v[e] * s1[o] + t1[o];
            v[e] = t / (1.0f + __expf(-t));
        }
        hp4[i] = make_float4(v[0], v[1], v[2], v[3]);
    }
}

// ---------------------------------------------------------------------------
// Stage 2: out = einsum(h[nbr], w2) + z
//   - warp processes 64 nodes (thread handles 2 nodes: M=2 weight reuse)
//   - cooperative gather: 8 lanes per 128B row, 4 rows per LDG.128
//   - smem staging with 36-float row stride (conflict-free)
//   - packed f32x2 accumulation
// ---------------------------------------------------------------------------
#define ROW_STRIDE 36                       // floats; 144B, 16B-aligned, odd/4
#define STAGE_PER_WARP (64 * ROW_STRIDE)    // 2304 floats

__global__ __launch_bounds__(256, 1) void stage2_kernel(
    const float* __restrict__ w2,
    float*       __restrict__ out,
    size_t half)
{
    extern __shared__ __align__(16) float smem[];
    float* w2s   = smem;                    // 27648 floats
    float* stage = smem + KK * FOUT * FOUT; // 8 * 2304 floats

    {
        const float4* src = (const float4*)w2;
        float4* dst = (float4*)w2s;
        for (int i = threadIdx.x; i < KK * FOUT * FOUT / 4; i += 256)
            dst[i] = src[i];
    }
    __syncthreads();

    const int warp = threadIdx.x >> 5;
    const int lane = threadIdx.x & 31;
    const int base = (blockIdx.x * 8 + warp) * 64;
    const int n0 = base + lane;
    const int n1 = base + 32 + lane;
    float* st = stage + warp * STAGE_PER_WARP;

    const int c    = lane & 7;   // 16B chunk within row
    const int rsub = lane >> 3;  // row-within-group (0..3)

    // accumulators initialized from point-branch z
    unsigned long long acc0[16], acc1[16];
    {
        const ulonglong2* zp0 = (const ulonglong2*)&g_z[(size_t)n0 * FOUT];
        const ulonglong2* zp1 = (const ulonglong2*)&g_z[(size_t)n1 * FOUT];
        #pragma unroll
        for (int i = 0; i < 8; i++) {
            ulonglong2 a = zp0[i]; acc0[2*i] = a.x; acc0[2*i+1] = a.y;
            ulonglong2 b = zp1[i]; acc1[2*i] = b.x; acc1[2*i+1] = b.y;
        }
    }

    #pragma unroll 1
    for (int k = 0; k < KK; k++) {
        const int j0 = g_nbrT[(size_t)k * NN + n0];   // coalesced
        const int j1 = g_nbrT[(size_t)k * NN + n1];

        // cooperative gather: 16 iterations x 4 rows, 8 lanes per row
        #pragma unroll
        for (int i = 0; i < 16; i++) {
            const int m = 4 * i + rsub;               // row 0..63
            const int jj = __shfl_sync(0xffffffffu, (i < 8) ? j0 : j1, m & 31);
            const float4 v = __ldg((const float4*)(g_h + (size_t)jj * FOUT) + c);
            *(float4*)(st + m * ROW_STRIDE + c * 4) = v;
        }
        __syncwarp();

        // readback own rows (conflict-free: stride 36 floats)
        float r0[FOUT], r1[FOUT];
        {
            const float4* p0 = (const float4*)(st + lane * ROW_STRIDE);
            const float4* p1 = (const float4*)(st + (lane + 32) * ROW_STRIDE);
            #pragma unroll
            for (int i = 0; i < 8; i++) {
                float4 a = p0[i];
                r0[4*i] = a.x; r0[4*i+1] = a.y; r0[4*i+2] = a.z; r0[4*i+3] = a.w;
                float4 b = p1[i];
                r1[4*i] = b.x; r1[4*i+1] = b.y; r1[4*i+2] = b.z; r1[4*i+3] = b.w;
            }
        }

        // accumulate: each weight load feeds BOTH nodes (M=2 reuse)
        const double2* w = (const double2*)(w2s + k * (FOUT * FOUT));
        #pragma unroll
        for (int f = 0; f < FOUT; f++) {
            unsigned int h0u = __float_as_uint(r0[f]);
            unsigned int h1u = __float_as_uint(r1[f]);
            unsigned long long hp0, hp1;
            asm("mov.b64 %0, {%1, %1};" : "=l"(hp0) : "r"(h0u));
            asm("mov.b64 %0, {%1, %1};" : "=l"(hp1) : "r"(h1u));
            #pragma unroll
            for (int p = 0; p < 8; p++) {
                double2 wv = w[f * 8 + p];
                unsigned long long w0 = __double_as_longlong(wv.x);
                unsigned long long w1v = __double_as_longlong(wv.y);
                asm("fma.rn.f32x2 %0, %1, %2, %0;" : "+l"(acc0[2*p])   : "l"(hp0), "l"(w0));
                asm("fma.rn.f32x2 %0, %1, %2, %0;" : "+l"(acc0[2*p+1]) : "l"(hp0), "l"(w1v));
                asm("fma.rn.f32x2 %0, %1, %2, %0;" : "+l"(acc1[2*p])   : "l"(hp1), "l"(w0));
                asm("fma.rn.f32x2 %0, %1, %2, %0;" : "+l"(acc1[2*p+1]) : "l"(hp1), "l"(w1v));
            }
        }
        __syncwarp();   // protect staging buffer before next k overwrites
    }

    // write both output halves for both nodes
    {
        ulonglong2* o0a = (ulonglong2*)(out + (size_t)n0 * FOUT);
        ulonglong2* o0b = (ulonglong2*)(out + half + (size_t)n0 * FOUT);
        ulonglong2* o1a = (ulonglong2*)(out + (size_t)n1 * FOUT);
        ulonglong2* o1b = (ulonglong2*)(out + half + (size_t)n1 * FOUT);
        #pragma unroll
        for (int i = 0; i < 8; i++) {
            ulonglong2 a; a.x = acc0[2*i]; a.y = acc0[2*i+1];
            o0a[i] = a; o0b[i] = a;
            ulonglong2 b; b.x = acc1[2*i]; b.y = acc1[2*i+1];
            o1a[i] = b; o1b[i] = b;
        }
    }
}

// ---------------------------------------------------------------------------
extern "C" void kernel_launch(void* const* d_in, const int* in_sizes, int n_in,
                              void* d_out, int out_size)
{
    const float* x_feats   = (const float*)d_in[0];
    const float* z_feats   = (const float*)d_in[1];
    const int*   nbr_idx   = (const int*)  d_in[2];
    const float* w1        = (const float*)d_in[3];
    const float* bn1_gamma = (const float*)d_in[4];
    const float* bn1_beta  = (const float*)d_in[5];
    const float* bn1_mean  = (const float*)d_in[6];
    const float* bn1_var   = (const float*)d_in[7];
    const float* w2        = (const float*)d_in[8];
    const float* mlp_w     = (const float*)d_in[9];
    const float* mlp_b     = (const float*)d_in[10];
    const float* mlp_gamma = (const float*)d_in[11];
    const float* mlp_beta  = (const float*)d_in[12];
    const float* mlp_mean  = (const float*)d_in[13];
    const float* mlp_var   = (const float*)d_in[14];

    float* out = (float*)d_out;
    const size_t half = (size_t)out_size / 2;

    static bool attr_done = false;
    const int smem2 = (KK * FOUT * FOUT + 8 * STAGE_PER_WARP) * (int)sizeof(float);
    if (!attr_done) {
        cudaFuncSetAttribute(stage2_kernel,
                             cudaFuncAttributeMaxDynamicSharedMemorySize, smem2);
        attr_done = true;
    }

    const int prep_blocks = (NN * KK + 255) / 256;
    prep_kernel<<<prep_blocks, 256>>>(x_feats, nbr_idx);

    stage1_kernel<<<NN / 256, 256>>>(z_feats, w1,
                                     bn1_gamma, bn1_beta, bn1_mean, bn1_var,
                                     mlp_w, mlp_b, mlp_gamma, mlp_beta,
                                     mlp_mean, mlp_var);

    stage2_kernel<<<NN / (64 * 8), 256, smem2>>>(w2, out, half);
}

// round 5
// speedup vs baseline: 2.2656x; 1.4867x over previous
#include <cuda_runtime.h>
#include <cuda_fp16.h>
#include <cstdint>
#include <cstddef>

#define NN 131072
#define KK 27
#define FIN 3
#define FOUT 32
#define EPSV 1e-5f

// ---------------- device scratch (no allocation allowed) ----------------
__device__ float  g_z[(size_t)NN * FOUT];
__device__ uint4  g_h16[(size_t)NN * 8];   // per node 128B: [fp16 hi f0..31 | fp16 lo f0..31]
__device__ float4 g_x4[(size_t)NN];
__device__ int    g_nbrT[(size_t)KK * NN];
// B fragments in mma layout: [k][slot=kchunk*4+ntile][lane] -> {bhi0,bhi1,blo0,blo1}
__device__ uint4  g_wfrag[KK * 8 * 32];

__device__ __forceinline__ uint32_t smem_u32(const void* p) {
    uint32_t a;
    asm("{ .reg .u64 t; cvta.to.shared.u64 t, %1; cvt.u32.u64 %0, t; }" : "=r"(a) : "l"(p));
    return a;
}

__device__ __forceinline__ uint32_t pack_h2(float a, float b) {
    const __half ha = __float2half_rn(a);
    const __half hb = __float2half_rn(b);
    return (uint32_t)__half_as_ushort(ha) | ((uint32_t)__half_as_ushort(hb) << 16);
}

#define LDSM4(r, addr) \
    asm volatile("ldmatrix.sync.aligned.m8n8.x4.shared.b16 {%0,%1,%2,%3}, [%4];" \
        : "=r"((r)[0]), "=r"((r)[1]), "=r"((r)[2]), "=r"((r)[3]) : "r"(addr))

#define MMA16816(d, a, b0, b1) \
    asm volatile("mma.sync.aligned.m16n8k16.row.col.f32.f16.f16.f32 " \
        "{%0,%1,%2,%3}, {%4,%5,%6,%7}, {%8,%9}, {%0,%1,%2,%3};" \
        : "+f"((d)[0]), "+f"((d)[1]), "+f"((d)[2]), "+f"((d)[3]) \
        : "r"((a)[0]), "r"((a)[1]), "r"((a)[2]), "r"((a)[3]), "r"(b0), "r"(b1))

// ---------------- prep: transpose nbr, pad x, build B-fragment image ----------------
__global__ __launch_bounds__(256) void prep_kernel(
    const float* __restrict__ x_feats,
    const int*   __restrict__ nbr,
    const float* __restrict__ w2)
{
    const size_t i = (size_t)blockIdx.x * 256 + threadIdx.x;
    if (i < (size_t)NN * KK) {
        const int v = nbr[i];
        const int n = (int)(i / KK);
        const int k = (int)(i % KK);
        g_nbrT[(size_t)k * NN + n] = v;
    }
    if (i < NN)
        g_x4[i] = make_float4(x_feats[3*i], x_feats[3*i+1], x_feats[3*i+2], 0.0f);
    if (i < (size_t)KK * 8 * 32) {
        const int lane  = (int)(i & 31);
        const int slot  = (int)((i >> 5) & 7);
        const int k     = (int)(i >> 8);
        const int kc    = slot >> 2;
        const int ntile = slot & 3;
        const int o  = ntile * 8 + (lane >> 2);
        const int f0 = kc * 16 + (lane & 3) * 2;
        const float w00 = w2[(k*32 + f0    )*32 + o];
        const float w01 = w2[(k*32 + f0 + 1)*32 + o];
        const float w10 = w2[(k*32 + f0 + 8)*32 + o];
        const float w11 = w2[(k*32 + f0 + 9)*32 + o];
        const float h00 = __half2float(__float2half_rn(w00));
        const float h01 = __half2float(__float2half_rn(w01));
        const float h10 = __half2float(__float2half_rn(w10));
        const float h11 = __half2float(__float2half_rn(w11));
        uint4 r;
        r.x = pack_h2(w00, w01);                 // Bhi b0
        r.y = pack_h2(w10, w11);                 // Bhi b1
        r.z = pack_h2(w00 - h00, w01 - h01);     // Blo b0
        r.w = pack_h2(w10 - h10, w11 - h11);     // Blo b1
        g_wfrag[i] = r;
    }
}

// ---------------- stage 1: h = silu(bn1(gather(x)@w1)) split fp16; z branch ----------
__global__ __launch_bounds__(256) void stage1_kernel(
    const float* __restrict__ z_feats,
    const float* __restrict__ w1,
    const float* __restrict__ bn1_gamma,
    const float* __restrict__ bn1_beta,
    const float* __restrict__ bn1_mean,
    const float* __restrict__ bn1_var,
    const float* __restrict__ mlp_w,
    const float* __restrict__ mlp_b,
    const float* __restrict__ mlp_gamma,
    const float* __restrict__ mlp_beta,
    const float* __restrict__ mlp_mean,
    const float* __restrict__ mlp_var)
{
    __shared__ __align__(16) float w1s[KK * FIN * FOUT];
    __shared__ __align__(16) float mws[FIN * FOUT];
    __shared__ float s1[FOUT], t1[FOUT], s2[FOUT], t2[FOUT], mbs[FOUT];

    const int tid = threadIdx.x;
    for (int i = tid; i < KK * FIN * FOUT; i += 256) w1s[i] = w1[i];
    for (int i = tid; i < FIN * FOUT; i += 256) mws[i] = mlp_w[i];
    if (tid < FOUT) {
        float s = bn1_gamma[tid] * rsqrtf(bn1_var[tid] + EPSV);
        s1[tid] = s;
        t1[tid] = bn1_beta[tid] - bn1_mean[tid] * s;
        float q = mlp_gamma[tid] * rsqrtf(mlp_var[tid] + EPSV);
        s2[tid] = q;
        t2[tid] = mlp_beta[tid] - mlp_mean[tid] * q;
        mbs[tid] = mlp_b[tid];
    }
    __syncthreads();

    const int n = blockIdx.x * 256 + tid;

    // ---- point branch ----
    {
        float acc[FOUT];
        const float zf0 = z_feats[(size_t)n * 3 + 0];
        const float zf1 = z_feats[(size_t)n * 3 + 1];
        const float zf2 = z_feats[(size_t)n * 3 + 2];
        #pragma unroll
        for (int o = 0; o < FOUT; o++) {
            float v = zf0 * mws[o] + zf1 * mws[FOUT + o] + zf2 * mws[2 * FOUT + o] + mbs[o];
            v = v * s2[o] + t2[o];
            acc[o] = fmaxf(v, 0.0f);
        }
        float4* zp = (float4*)&g_z[(size_t)n * FOUT];
        #pragma unroll
        for (int i = 0; i < 8; i++)
            zp[i] = make_float4(acc[4*i], acc[4*i+1], acc[4*i+2], acc[4*i+3]);
    }

    // ---- voxel branch stage 1, packed f32x2 ----
    unsigned long long acc[16];
    #pragma unroll
    for (int i = 0; i < 16; i++) acc[i] = 0ull;

    #pragma unroll 1
    for (int k = 0; k < KK; k++) {
        const int j = g_nbrT[(size_t)k * NN + n];
        const float4 xv = __ldg(&g_x4[j]);
        const float xs[3] = {xv.x, xv.y, xv.z};
        const double2* w = (const double2*)&w1s[k * FIN * FOUT];
        #pragma unroll
        for (int f = 0; f < FIN; f++) {
            unsigned int hu = __float_as_uint(xs[f]);
            unsigned long long hp;
            asm("mov.b64 %0, {%1, %1};" : "=l"(hp) : "r"(hu));
            #pragma unroll
            for (int p = 0; p < 8; p++) {
                double2 wv = w[f * 8 + p];
                unsigned long long w0 = __double_as_longlong(wv.x);
                unsigned long long w1v = __double_as_longlong(wv.y);
                asm("fma.rn.f32x2 %0, %1, %2, %0;" : "+l"(acc[2*p])   : "l"(hp), "l"(w0));
                asm("fma.rn.f32x2 %0, %1, %2, %0;" : "+l"(acc[2*p+1]) : "l"(hp), "l"(w1v));
            }
        }
    }

    // BN + SiLU, split to fp16 hi/lo, pack 128B row
    uint32_t hw[16], lw[16];
    #pragma unroll
    for (int p = 0; p < 16; p++) {
        const unsigned long long a = acc[p];
        float v0 = __uint_as_float((unsigned int)(a & 0xffffffffull));
        float v1 = __uint_as_float((unsigned int)(a >> 32));
        const int o0 = 2*p, o1 = 2*p + 1;
        v0 = v0 * s1[o0] + t1[o0]; v0 = v0 / (1.0f + __expf(-v0));
        v1 = v1 * s1[o1] + t1[o1]; v1 = v1 / (1.0f + __expf(-v1));
        const float h0 = __half2float(__float2half_rn(v0));
        const float h1 = __half2float(__float2half_rn(v1));
        hw[p] = pack_h2(v0, v1);
        lw[p] = pack_h2(v0 - h0, v1 - h1);
    }
    uint4* row = &g_h16[(size_t)n * 8];
    #pragma unroll
    for (int q = 0; q < 4; q++)
        row[q] = make_uint4(hw[4*q], hw[4*q+1], hw[4*q+2], hw[4*q+3]);
    #pragma unroll
    for (int q = 0; q < 4; q++)
        row[4 + q] = make_uint4(lw[4*q], lw[4*q+1], lw[4*q+2], lw[4*q+3]);
}

// ---------------- stage 2: mma.sync gather-GEMM ----------------
// Each warp: one 16-node tile. D(16x32) = sum_k A_k(16x32) @ W_k(32x32), + z.
// A from gathered pre-split fp16 rows staged in smem (stride 144B, double-buffered).
// B fragments from precomputed g_wfrag (L1-resident, coalesced).
__global__ __launch_bounds__(256) void stage2_kernel(
    float* __restrict__ out, size_t half)
{
    __shared__ uint4 stage[8][2][16 * 9];   // 8 warps x 2 bufs x (16 rows x 144B)

    const int tid  = threadIdx.x;
    const int warp = tid >> 5;
    const int lane = tid & 31;
    const int tb   = blockIdx.x * 128 + warp * 16;   // tile base node

    const int c    = lane & 7;      // 16B chunk in row
    const int rsub = lane >> 3;     // 0..3

    float d[4][4];
    #pragma unroll
    for (int nt = 0; nt < 4; nt++)
        #pragma unroll
        for (int e = 0; e < 4; e++) d[nt][e] = 0.0f;

    // prologue: gather k=0 into buf 0
    {
        const int* idxp = g_nbrT + 0 * (size_t)NN + tb;
        const int j = __ldg(&idxp[lane & 15]);
        #pragma unroll
        for (int r = 0; r < 4; r++) {
            const int row = r * 4 + rsub;
            const int jr = __shfl_sync(0xffffffffu, j, row);
            stage[warp][0][row * 9 + c] = __ldg(&g_h16[(size_t)jr * 8 + c]);
        }
    }

    int b = 0;
    #pragma unroll 1
    for (int k = 0; k < KK; k++) {
        // B fragments for this k (coalesced, L1-resident after first touch)
        uint4 bf[8];
        {
            const uint4* wf = g_wfrag + (size_t)k * 256 + lane;
            #pragma unroll
            for (int s = 0; s < 8; s++) bf[s] = __ldg(&wf[s * 32]);
        }

        // prefetch gather for k+1 into registers
        uint4 v[4];
        int have_next = (k + 1 < KK);
        if (have_next) {
            const int* idxp = g_nbrT + (size_t)(k + 1) * NN + tb;
            const int j = __ldg(&idxp[lane & 15]);
            #pragma unroll
            for (int r = 0; r < 4; r++) {
                const int row = r * 4 + rsub;
                const int jr = __shfl_sync(0xffffffffu, j, row);
                v[r] = __ldg(&g_h16[(size_t)jr * 8 + c]);
            }
        }

        __syncwarp();

        // A fragments from stage[warp][b]
        const uint32_t abase = smem_u32(&stage[warp][b][0]);
        const uint32_t addr0 = abase + (uint32_t)(lane & 15) * 144 + (uint32_t)((lane >> 4) << 4);
        uint32_t ah0[4], ah1[4], al0[4], al1[4];
        LDSM4(ah0, addr0);        // hi, f0-15
        LDSM4(ah1, addr0 + 32);   // hi, f16-31
        LDSM4(al0, addr0 + 64);   // lo, f0-15
        LDSM4(al1, addr0 + 96);   // lo, f16-31

        // store prefetched rows into the other buffer
        if (have_next) {
            #pragma unroll
            for (int r = 0; r < 4; r++)
                stage[warp][b ^ 1][(r * 4 + rsub) * 9 + c] = v[r];
        }

        // 24 MMAs: Ahi*Bhi + Ahi*Blo + Alo*Bhi
        #pragma unroll
        for (int nt = 0; nt < 4; nt++) {
            const uint4 b0 = bf[nt];        // kchunk 0
            MMA16816(d[nt], ah0, b0.x, b0.y);
            MMA16816(d[nt], ah0, b0.z, b0.w);
            MMA16816(d[nt], al0, b0.x, b0.y);
            const uint4 b1 = bf[4 + nt];    // kchunk 1
            MMA16816(d[nt], ah1, b1.x, b1.y);
            MMA16816(d[nt], ah1, b1.z, b1.w);
            MMA16816(d[nt], al1, b1.x, b1.y);
        }
        b ^= 1;
    }

    // epilogue: + z, write both output halves
    const int row  = lane >> 2;
    const int colb = (lane & 3) * 2;
    const int n0 = tb + row;
    const int n1 = tb + row + 8;
    #pragma unroll
    for (int nt = 0; nt < 4; nt++) {
        const int col = nt * 8 + colb;
        const float2 z0 = *(const float2*)(g_z + (size_t)n0 * 32 + col);
        const float2 z1 = *(const float2*)(g_z + (size_t)n1 * 32 + col);
        float2 o0 = make_float2(d[nt][0] + z0.x, d[nt][1] + z0.y);
        float2 o1 = make_float2(d[nt][2] + z1.x, d[nt][3] + z1.y);
        *(float2*)(out + (size_t)n0 * 32 + col)        = o0;
        *(float2*)(out + half + (size_t)n0 * 32 + col) = o0;
        *(float2*)(out + (size_t)n1 * 32 + col)        = o1;
        *(float2*)(out + half + (size_t)n1 * 32 + col) = o1;
    }
}

// ---------------------------------------------------------------------------
extern "C" void kernel_launch(void* const* d_in, const int* in_sizes, int n_in,
                              void* d_out, int out_size)
{
    const float* x_feats   = (const float*)d_in[0];
    const float* z_feats   = (const float*)d_in[1];
    const int*   nbr_idx   = (const int*)  d_in[2];
    const float* w1        = (const float*)d_in[3];
    const float* bn1_gamma = (const float*)d_in[4];
    const float* bn1_beta  = (const float*)d_in[5];
    const float* bn1_mean  = (const float*)d_in[6];
    const float* bn1_var   = (const float*)d_in[7];
    const float* w2        = (const float*)d_in[8];
    const float* mlp_w     = (const float*)d_in[9];
    const float* mlp_b     = (const float*)d_in[10];
    const float* mlp_gamma = (const float*)d_in[11];
    const float* mlp_beta  = (const float*)d_in[12];
    const float* mlp_mean  = (const float*)d_in[13];
    const float* mlp_var   = (const float*)d_in[14];

    float* out = (float*)d_out;
    const size_t half = (size_t)out_size / 2;

    const int prep_blocks = (NN * KK + 255) / 256;
    prep_kernel<<<prep_blocks, 256>>>(x_feats, nbr_idx, w2);

    stage1_kernel<<<NN / 256, 256>>>(z_feats, w1,
                                     bn1_gamma, bn1_beta, bn1_mean, bn1_var,
                                     mlp_w, mlp_b, mlp_gamma, mlp_beta,
                                     mlp_mean, mlp_var);

    stage2_kernel<<<NN / 128, 256>>>(out, half);
}

// round 6
// speedup vs baseline: 3.3761x; 1.4902x over previous
#include <cuda_runtime.h>
#include <cuda_fp16.h>
#include <cstdint>
#include <cstddef>

#define NN 131072
#define KK 27
#define FIN 3
#define FOUT 32
#define EPSV 1e-5f

// ---------------- device scratch (no allocation allowed) ----------------
__device__ float  g_z[(size_t)NN * FOUT];
__device__ uint4  g_hh[(size_t)NN * 4];    // per node 64B: fp16 hi of h[0..31]
__device__ float4 g_x4[(size_t)NN];
__device__ int    g_nbrT[(size_t)KK * NN];
// B fragments in mma layout: [k][slot=kchunk*4+ntile][lane] -> {wh_b0,wh_b1,wl_b0,wl_b1}
__device__ uint4  g_wfrag[KK * 8 * 32];

__device__ __forceinline__ uint32_t smem_u32(const void* p) {
    uint32_t a;
    asm("{ .reg .u64 t; cvta.to.shared.u64 t, %1; cvt.u32.u64 %0, t; }" : "=r"(a) : "l"(p));
    return a;
}
__device__ __forceinline__ uint32_t pack_h2(float a, float b) {
    const __half ha = __float2half_rn(a);
    const __half hb = __float2half_rn(b);
    return (uint32_t)__half_as_ushort(ha) | ((uint32_t)__half_as_ushort(hb) << 16);
}

#define LDSM4(r, addr) \
    asm volatile("ldmatrix.sync.aligned.m8n8.x4.shared.b16 {%0,%1,%2,%3}, [%4];" \
        : "=r"((r)[0]), "=r"((r)[1]), "=r"((r)[2]), "=r"((r)[3]) : "r"(addr))

#define MMA16816(d, a, b0, b1) \
    asm volatile("mma.sync.aligned.m16n8k16.row.col.f32.f16.f16.f32 " \
        "{%0,%1,%2,%3}, {%4,%5,%6,%7}, {%8,%9}, {%0,%1,%2,%3};" \
        : "+f"((d)[0]), "+f"((d)[1]), "+f"((d)[2]), "+f"((d)[3]) \
        : "r"((a)[0]), "r"((a)[1]), "r"((a)[2]), "r"((a)[3]), "r"(b0), "r"(b1))

// ---------------- prep: tiled transpose + x pad + B-fragment image ----------------
// blocks [0,512): transpose 256-node tile + pad x4; blocks [512,539): wfrag
__global__ __launch_bounds__(256) void prep_kernel(
    const float* __restrict__ x_feats,
    const int*   __restrict__ nbr,
    const float* __restrict__ w2)
{
    const int tid = threadIdx.x;
    const int b   = blockIdx.x;
    if (b < NN / 256) {
        __shared__ int s[256 * KK];
        const int n0 = b * 256;
        const int* src = nbr + (size_t)n0 * KK;
        #pragma unroll
        for (int i = 0; i < KK; i++) s[tid + i * 256] = src[tid + i * 256];
        {
            const int n = n0 + tid;
            g_x4[n] = make_float4(x_feats[3*n], x_feats[3*n+1], x_feats[3*n+2], 0.0f);
        }
        __syncthreads();
        #pragma unroll 1
        for (int k = 0; k < KK; k++)
            g_nbrT[(size_t)k * NN + n0 + tid] = s[tid * KK + k];
    } else {
        const int i = (b - NN / 256) * 256 + tid;      // 0 .. KK*8*32-1
        const int lane  = i & 31;
        const int slot  = (i >> 5) & 7;
        const int k     = i >> 8;
        const int kc    = slot >> 2;
        const int ntile = slot & 3;
        const int o  = ntile * 8 + (lane >> 2);
        const int f0 = kc * 16 + (lane & 3) * 2;
        const float w00 = w2[(k*32 + f0    )*32 + o];
        const float w01 = w2[(k*32 + f0 + 1)*32 + o];
        const float w10 = w2[(k*32 + f0 + 8)*32 + o];
        const float w11 = w2[(k*32 + f0 + 9)*32 + o];
        const float h00 = __half2float(__float2half_rn(w00));
        const float h01 = __half2float(__float2half_rn(w01));
        const float h10 = __half2float(__float2half_rn(w10));
        const float h11 = __half2float(__float2half_rn(w11));
        uint4 r;
        r.x = pack_h2(w00, w01);                 // W hi, b0
        r.y = pack_h2(w10, w11);                 // W hi, b1
        r.z = pack_h2(w00 - h00, w01 - h01);     // W lo, b0
        r.w = pack_h2(w10 - h10, w11 - h11);     // W lo, b1
        g_wfrag[i] = r;
    }
}

// ---------------- stage 1 ----------------
__global__ __launch_bounds__(256) void stage1_kernel(
    const float* __restrict__ z_feats,
    const float* __restrict__ w1,
    const float* __restrict__ bn1_gamma,
    const float* __restrict__ bn1_beta,
    const float* __restrict__ bn1_mean,
    const float* __restrict__ bn1_var,
    const float* __restrict__ mlp_w,
    const float* __restrict__ mlp_b,
    const float* __restrict__ mlp_gamma,
    const float* __restrict__ mlp_beta,
    const float* __restrict__ mlp_mean,
    const float* __restrict__ mlp_var)
{
    __shared__ __align__(16) float w1s[KK * FIN * FOUT];
    __shared__ __align__(16) float mws[FIN * FOUT];
    __shared__ float s1[FOUT], t1[FOUT], s2[FOUT], t2[FOUT], mbs[FOUT];

    const int tid = threadIdx.x;
    for (int i = tid; i < KK * FIN * FOUT; i += 256) w1s[i] = w1[i];
    for (int i = tid; i < FIN * FOUT; i += 256) mws[i] = mlp_w[i];
    if (tid < FOUT) {
        float s = bn1_gamma[tid] * rsqrtf(bn1_var[tid] + EPSV);
        s1[tid] = s;
        t1[tid] = bn1_beta[tid] - bn1_mean[tid] * s;
        float q = mlp_gamma[tid] * rsqrtf(mlp_var[tid] + EPSV);
        s2[tid] = q;
        t2[tid] = mlp_beta[tid] - mlp_mean[tid] * q;
        mbs[tid] = mlp_b[tid];
    }
    __syncthreads();

    const int n = blockIdx.x * 256 + tid;

    // ---- point branch ----
    {
        float acc[FOUT];
        const float zf0 = z_feats[(size_t)n * 3 + 0];
        const float zf1 = z_feats[(size_t)n * 3 + 1];
        const float zf2 = z_feats[(size_t)n * 3 + 2];
        #pragma unroll
        for (int o = 0; o < FOUT; o++) {
            float v = zf0 * mws[o] + zf1 * mws[FOUT + o] + zf2 * mws[2 * FOUT + o] + mbs[o];
            v = v * s2[o] + t2[o];
            acc[o] = fmaxf(v, 0.0f);
        }
        float4* zp = (float4*)&g_z[(size_t)n * FOUT];
        #pragma unroll
        for (int i = 0; i < 8; i++)
            zp[i] = make_float4(acc[4*i], acc[4*i+1], acc[4*i+2], acc[4*i+3]);
    }

    // ---- voxel branch stage 1, packed f32x2 ----
    unsigned long long acc[16];
    #pragma unroll
    for (int i = 0; i < 16; i++) acc[i] = 0ull;

    #pragma unroll 1
    for (int k = 0; k < KK; k++) {
        const int j = g_nbrT[(size_t)k * NN + n];
        const float4 xv = __ldg(&g_x4[j]);
        const float xs[3] = {xv.x, xv.y, xv.z};
        const double2* w = (const double2*)&w1s[k * FIN * FOUT];
        #pragma unroll
        for (int f = 0; f < FIN; f++) {
            unsigned int hu = __float_as_uint(xs[f]);
            unsigned long long hp;
            asm("mov.b64 %0, {%1, %1};" : "=l"(hp) : "r"(hu));
            #pragma unroll
            for (int p = 0; p < 8; p++) {
                double2 wv = w[f * 8 + p];
                unsigned long long w0 = __double_as_longlong(wv.x);
                unsigned long long w1v = __double_as_longlong(wv.y);
                asm("fma.rn.f32x2 %0, %1, %2, %0;" : "+l"(acc[2*p])   : "l"(hp), "l"(w0));
                asm("fma.rn.f32x2 %0, %1, %2, %0;" : "+l"(acc[2*p+1]) : "l"(hp), "l"(w1v));
            }
        }
    }

    // BN + SiLU, round to fp16 hi, pack 64B row
    uint32_t hw[16];
    #pragma unroll
    for (int p = 0; p < 16; p++) {
        const unsigned long long a = acc[p];
        float v0 = __uint_as_float((unsigned int)(a & 0xffffffffull));
        float v1 = __uint_as_float((unsigned int)(a >> 32));
        const int o0 = 2*p, o1 = 2*p + 1;
        v0 = v0 * s1[o0] + t1[o0]; v0 = v0 / (1.0f + __expf(-v0));
        v1 = v1 * s1[o1] + t1[o1]; v1 = v1 / (1.0f + __expf(-v1));
        hw[p] = pack_h2(v0, v1);
    }
    uint4* row = &g_hh[(size_t)n * 4];
    #pragma unroll
    for (int q = 0; q < 4; q++)
        row[q] = make_uint4(hw[4*q], hw[4*q+1], hw[4*q+2], hw[4*q+3]);
}

// ---------------- stage 2: mma.sync gather-GEMM, M=32/warp, 2-pass fp16 ----------------
// D(32x32) = sum_k A_k(32x32) @ (Wh_k + Wl_k), + z. A = fp16(h) gathered.
// Stage rows: 64B data, 80B stride (conflict-free ldmatrix).
__global__ __launch_bounds__(256) void stage2_kernel(
    float* __restrict__ out, size_t half)
{
    __shared__ uint4 stage[8][2][32 * 5];   // 8 warps x 2 bufs x (32 rows x 80B) = 40KB

    const int tid  = threadIdx.x;
    const int warp = tid >> 5;
    const int lane = tid & 31;
    const int tb   = blockIdx.x * 256 + warp * 32;   // tile base node

    const int gr = lane >> 2;   // row-within-group 0..7
    const int gc = lane & 3;    // 16B chunk 0..3

    float d[2][4][4];
    #pragma unroll
    for (int t = 0; t < 2; t++)
        #pragma unroll
        for (int nt = 0; nt < 4; nt++)
            #pragma unroll
            for (int e = 0; e < 4; e++) d[t][nt][e] = 0.0f;

    // prologue: gather k=0 into buf 0
    {
        const int j = __ldg(g_nbrT + tb + lane);
        #pragma unroll
        for (int r = 0; r < 4; r++) {
            const int row = r * 8 + gr;
            const int jr = __shfl_sync(0xffffffffu, j, row);
            stage[warp][0][row * 5 + gc] = __ldg(&g_hh[(size_t)jr * 4 + gc]);
        }
    }

    int b = 0;
    #pragma unroll 1
    for (int k = 0; k < KK; k++) {
        // B fragments for this k (coalesced, L1-resident)
        uint4 bf[8];
        {
            const uint4* wf = g_wfrag + (size_t)k * 256 + lane;
            #pragma unroll
            for (int s = 0; s < 8; s++) bf[s] = __ldg(&wf[s * 32]);
        }

        // prefetch gather for k+1 into registers
        uint4 v[4];
        const int have_next = (k + 1 < KK);
        if (have_next) {
            const int j = __ldg(g_nbrT + (size_t)(k + 1) * NN + tb + lane);
            #pragma unroll
            for (int r = 0; r < 4; r++) {
                const int row = r * 8 + gr;
                const int jr = __shfl_sync(0xffffffffu, j, row);
                v[r] = __ldg(&g_hh[(size_t)jr * 4 + gc]);
            }
        }

        __syncwarp();

        // A fragments (hi only) from stage[warp][b]
        uint32_t a0[8], a1[8];   // tile 0 / tile 1: [ah_f0-15 x4 | ah_f16-31 x4]
        {
            const uint32_t abase = smem_u32(&stage[warp][b][0]);
            const uint32_t off = (uint32_t)(lane & 15) * 80 + (uint32_t)((lane >> 4) << 4);
            LDSM4(a0,     abase + off);
            LDSM4(a0 + 4, abase + off + 32);
            LDSM4(a1,     abase + 16 * 80 + off);
            LDSM4(a1 + 4, abase + 16 * 80 + off + 32);
        }

        // store prefetched rows into the other buffer
        if (have_next) {
            #pragma unroll
            for (int r = 0; r < 4; r++)
                stage[warp][b ^ 1][(r * 8 + gr) * 5 + gc] = v[r];
        }

        // 32 MMAs: (Ah*Wh + Ah*Wl) for both 16-row tiles
        #pragma unroll
        for (int nt = 0; nt < 4; nt++) {
            const uint4 b0 = bf[nt];        // kchunk 0 (f0-15)
            const uint4 b1 = bf[4 + nt];    // kchunk 1 (f16-31)
            MMA16816(d[0][nt], a0,     b0.x, b0.y);
            MMA16816(d[0][nt], a0,     b0.z, b0.w);
            MMA16816(d[0][nt], a0 + 4, b1.x, b1.y);
            MMA16816(d[0][nt], a0 + 4, b1.z, b1.w);
            MMA16816(d[1][nt], a1,     b0.x, b0.y);
            MMA16816(d[1][nt], a1,     b0.z, b0.w);
            MMA16816(d[1][nt], a1 + 4, b1.x, b1.y);
            MMA16816(d[1][nt], a1 + 4, b1.z, b1.w);
        }
        b ^= 1;
    }

    // epilogue: + z, write both output halves
    const int row  = lane >> 2;
    const int colb = (lane & 3) * 2;
    #pragma unroll
    for (int t = 0; t < 2; t++) {
        const int n0 = tb + t * 16 + row;
        const int n1 = n0 + 8;
        #pragma unroll
        for (int nt = 0; nt < 4; nt++) {
            const int col = nt * 8 + colb;
            const float2 z0 = *(const float2*)(g_z + (size_t)n0 * 32 + col);
            const float2 z1 = *(const float2*)(g_z + (size_t)n1 * 32 + col);
            float2 o0 = make_float2(d[t][nt][0] + z0.x, d[t][nt][1] + z0.y);
            float2 o1 = make_float2(d[t][nt][2] + z1.x, d[t][nt][3] + z1.y);
            *(float2*)(out + (size_t)n0 * 32 + col)        = o0;
            *(float2*)(out + half + (size_t)n0 * 32 + col) = o0;
            *(float2*)(out + (size_t)n1 * 32 + col)        = o1;
            *(float2*)(out + half + (size_t)n1 * 32 + col) = o1;
        }
    }
}

// ---------------------------------------------------------------------------
extern "C" void kernel_launch(void* const* d_in, const int* in_sizes, int n_in,
                              void* d_out, int out_size)
{
    const float* x_feats   = (const float*)d_in[0];
    const float* z_feats   = (const float*)d_in[1];
    const int*   nbr_idx   = (const int*)  d_in[2];
    const float* w1        = (const float*)d_in[3];
    const float* bn1_gamma = (const float*)d_in[4];
    const float* bn1_beta  = (const float*)d_in[5];
    const float* bn1_mean  = (const float*)d_in[6];
    const float* bn1_var   = (const float*)d_in[7];
    const float* w2        = (const float*)d_in[8];
    const float* mlp_w     = (const float*)d_in[9];
    const float* mlp_b     = (const float*)d_in[10];
    const float* mlp_gamma = (const float*)d_in[11];
    const float* mlp_beta  = (const float*)d_in[12];
    const float* mlp_mean  = (const float*)d_in[13];
    const float* mlp_var   = (const float*)d_in[14];

    float* out = (float*)d_out;
    const size_t half = (size_t)out_size / 2;

    prep_kernel<<<NN / 256 + KK, 256>>>(x_feats, nbr_idx, w2);

    stage1_kernel<<<NN / 256, 256>>>(z_feats, w1,
                                     bn1_gamma, bn1_beta, bn1_mean, bn1_var,
                                     mlp_w, mlp_b, mlp_gamma, mlp_beta,
                                     mlp_mean, mlp_var);

    stage2_kernel<<<NN / 256, 256>>>(out, half);
}